// round 6
// baseline (speedup 1.0000x reference)
#include <cuda_runtime.h>

#define BB  4096
#define TT  500
#define FF  40
#define HH  128
#define OO  5
#define NB  4          // batches per warp
#define BETA 0.9f
#define THR  1.0f

#define LUT_FLOATS (OO * 16 * 256)              // 20480
#define STG_FLOATS (4 * 2 * NB * (2 * FF))      // 2560 (duplicated x)
#define DYN_SMEM   ((LUT_FLOATS + STG_FLOATS) * 4)

typedef unsigned long long u64;
typedef unsigned int u32;

__device__ float4 g_lut4[LUT_FLOATS / 4];

__device__ __forceinline__ u64 pack2(float lo, float hi) {
    u64 r; asm("mov.b64 %0, {%1, %2};" : "=l"(r) : "f"(lo), "f"(hi)); return r;
}
__device__ __forceinline__ void unpack2(u64 v, float& lo, float& hi) {
    asm("mov.b64 {%0, %1}, %2;" : "=f"(lo), "=f"(hi) : "l"(v));
}
__device__ __forceinline__ u64 fma2(u64 a, u64 b, u64 c) {
    u64 d; asm("fma.rn.f32x2 %0, %1, %2, %3;" : "=l"(d) : "l"(a), "l"(b), "l"(c)); return d;
}

// LUT[o][seg][v] = sum_{j ascending, bit j set in v} W2[o][seg*8 + j]
__global__ void build_lut_kernel(const float* __restrict__ W2) {
    const int idx = blockIdx.x * blockDim.x + threadIdx.x;
    if (idx >= LUT_FLOATS) return;
    const int v = idx & 255, seg = (idx >> 8) & 15, o = idx >> 12;
    float s = 0.f;
#pragma unroll
    for (int j = 0; j < 8; j++)
        if (v & (1 << j)) s += W2[o * HH + seg * 8 + j];
    ((float*)g_lut4)[idx] = s;
}

// 1 warp = 4 batch elements; W1 shared in registers (8 packed-FMA chains).
// x staged in SMEM pre-duplicated ([x,x,y,y,...]) so LDS.128 yields packed
// f32x2 multipliers directly (no MOVs). Layer-1 per-neuron accumulation order
// (bias first, k ascending) identical to the bitwise-exact R1..R5 kernels.
// Layer 2 via ballot + byte-LUT (identical to rel_err=0 R5).
__global__ __launch_bounds__(128, 2)
void snn_kernel(const float* __restrict__ x,  const float* __restrict__ W1,
                const float* __restrict__ b1, const float* __restrict__ b2,
                float* __restrict__ out)
{
    extern __shared__ float smem_dyn[];
    float* lut = smem_dyn;                                        // 20480 floats
    float (*sbuf)[2][NB][2 * FF] =
        (float (*)[2][NB][2 * FF])(smem_dyn + LUT_FLOATS);

    const int lane = threadIdx.x & 31;
    const int warp = threadIdx.x >> 5;
    const int b0   = (blockIdx.x * 4 + warp) * NB;

    // ---- copy LUT global -> shared (one-time) ----
    for (int i = threadIdx.x; i < LUT_FLOATS / 4; i += 128)
        ((float4*)lut)[i] = g_lut4[i];

    const int n0 = lane, n1 = lane + 32, n2 = lane + 64, n3 = lane + 96;

    // ---- W1 packed pairs in registers (shared by all 4 batches) ----
    u64 wA[FF], wB[FF];
#pragma unroll
    for (int k = 0; k < FF; k++) {
        wA[k] = pack2(W1[n0 * FF + k], W1[n1 * FF + k]);
        wB[k] = pack2(W1[n2 * FF + k], W1[n3 * FF + k]);
    }
    const u64 biasA = pack2(b1[n0], b1[n1]);
    const u64 biasB = pack2(b1[n2], b1[n3]);

    const int   oid  = lane & 7;     // output id within batch group
    const int   qsel = lane >> 3;    // which batch this lane's output belongs to
    const float b2l  = b2[oid < OO ? oid : 0];
    const bool  do_store = (oid < OO);
    const float* lrow = lut + (oid < OO ? oid : 0) * (16 * 256);

    // ---- staging map: 40 float4-chunks (4 batches x 10) over 32 lanes ----
    const int  q1i = (lane >= 30) ? 3 : (lane >= 20) ? 2 : (lane >= 10) ? 1 : 0;
    const int  r1i = lane - q1i * 10;
    const bool do2 = (lane < 8);
    const int  r2i = lane + 2;       // second chunk: batch 3, quads 2..9

    const float* xg1 = x + (size_t)(b0 + q1i) * TT * FF + r1i * 4;
    const float* xg2 = x + (size_t)(b0 + 3)   * TT * FF + r2i * 4;
    float*       ob  = out + (size_t)b0 * OO;

    float m1v[NB][4];
#pragma unroll
    for (int b = 0; b < NB; b++)
#pragma unroll
        for (int i = 0; i < 4; i++) m1v[b][i] = 0.f;
    float m2v = 0.f;

    // ---- de-convoy skew: co-resident CTA pair (bid, bid+148) differ in bit 2 ----
    {
        float dummy = 1.0f;
        const int skew = ((blockIdx.x >> 2) & 1) * 96;
#pragma unroll 1
        for (int i = 0; i < skew; i++)
            asm volatile("add.f32 %0, %0, %0;" : "+f"(dummy));
        if (dummy == 1.5f) __stcs(ob, 0.0f);   // never true; keeps chain live
    }

    // ---- prologue: stage x[t=0] (duplicated layout) ----
    {
        const float4 xa = __ldcs((const float4*)xg1);
        *((float4*)&sbuf[warp][0][q1i][r1i * 8])     = make_float4(xa.x, xa.x, xa.y, xa.y);
        *((float4*)&sbuf[warp][0][q1i][r1i * 8 + 4]) = make_float4(xa.z, xa.z, xa.w, xa.w);
        if (do2) {
            const float4 xb = __ldcs((const float4*)xg2);
            *((float4*)&sbuf[warp][0][3][r2i * 8])     = make_float4(xb.x, xb.x, xb.y, xb.y);
            *((float4*)&sbuf[warp][0][3][r2i * 8 + 4]) = make_float4(xb.z, xb.z, xb.w, xb.w);
        }
    }
    __syncthreads();   // covers LUT copy + staging

    int stage = 0;
#pragma unroll 1
    for (int t = 0; t < TT; t++) {
        // prefetch x[t+1] (clamped)
        const int tn = (t + 1 < TT) ? t + 1 : TT - 1;
        const float4 xa = __ldcs((const float4*)(xg1 + (size_t)tn * FF));
        float4 xb;
        if (do2) xb = __ldcs((const float4*)(xg2 + (size_t)tn * FF));

        // ---- layer 1: 4 batches = 8 independent packed-FMA chains,
        //      multipliers come pre-packed straight from LDS.128 ----
        u64 acc[NB][2];
#pragma unroll
        for (int b = 0; b < NB; b++) { acc[b][0] = biasA; acc[b][1] = biasB; }
#pragma unroll
        for (int j = 0; j < FF / 4; j++) {
#pragma unroll
            for (int b = 0; b < NB; b++) {
                const u64* p = (const u64*)&sbuf[warp][stage][b][j * 8];
                const u64 pxx = p[0], pyy = p[1], pzz = p[2], pww = p[3];
                acc[b][0] = fma2(pxx, wA[4*j+0], acc[b][0]);
                acc[b][1] = fma2(pxx, wB[4*j+0], acc[b][1]);
                acc[b][0] = fma2(pyy, wA[4*j+1], acc[b][0]);
                acc[b][1] = fma2(pyy, wB[4*j+1], acc[b][1]);
                acc[b][0] = fma2(pzz, wA[4*j+2], acc[b][0]);
                acc[b][1] = fma2(pzz, wB[4*j+2], acc[b][1]);
                acc[b][0] = fma2(pww, wA[4*j+3], acc[b][0]);
                acc[b][1] = fma2(pww, wB[4*j+3], acc[b][1]);
            }
        }

        // ---- LIF layer 1 + spike masks via ballot ----
        u32 mk[NB][4];
#pragma unroll
        for (int b = 0; b < NB; b++) {
            float cur[4];
            unpack2(acc[b][0], cur[0], cur[1]);
            unpack2(acc[b][1], cur[2], cur[3]);
#pragma unroll
            for (int i = 0; i < 4; i++) {
                const bool rst = m1v[b][i] > THR;
                float m = fmaf(BETA, m1v[b][i], cur[i]);
                if (rst) m -= THR;
                m1v[b][i] = m;
                mk[b][i] = __ballot_sync(0xffffffffu, m > THR);
            }
        }

        // ---- layer 2: byte-LUT lookups (ascending-h order) ----
        u32 ms[4];
#pragma unroll
        for (int i = 0; i < 4; i++)
            ms[i] = (qsel == 0) ? mk[0][i] : (qsel == 1) ? mk[1][i]
                  : (qsel == 2) ? mk[2][i] : mk[3][i];
        float a2 = 0.f;
#pragma unroll
        for (int i = 0; i < 4; i++) {
#pragma unroll
            for (int j = 0; j < 4; j++) {
                const u32 byte = (ms[i] >> (8 * j)) & 0xFFu;
                const float lv = lrow[(i * 4 + j) * 256 + byte];
                a2 = (i == 0 && j == 0) ? lv : (a2 + lv);
            }
        }

        // ---- LIF layer 2 + store (20 lanes active) ----
        const float cur2 = a2 + b2l;
        const bool rst2 = m2v > THR;
        float mm = fmaf(BETA, m2v, cur2);
        if (rst2) mm -= THR;
        m2v = mm;
        if (do_store)
            __stcs(ob + (size_t)t * BB * OO + qsel * OO + oid,
                   (mm > THR) ? 1.0f : 0.0f);

        // ---- stage x[t+1] (duplicated layout) ----
        *((float4*)&sbuf[warp][stage ^ 1][q1i][r1i * 8])     = make_float4(xa.x, xa.x, xa.y, xa.y);
        *((float4*)&sbuf[warp][stage ^ 1][q1i][r1i * 8 + 4]) = make_float4(xa.z, xa.z, xa.w, xa.w);
        if (do2) {
            *((float4*)&sbuf[warp][stage ^ 1][3][r2i * 8])     = make_float4(xb.x, xb.x, xb.y, xb.y);
            *((float4*)&sbuf[warp][stage ^ 1][3][r2i * 8 + 4]) = make_float4(xb.z, xb.z, xb.w, xb.w);
        }
        __syncwarp();
        stage ^= 1;
    }
}

extern "C" void kernel_launch(void* const* d_in, const int* in_sizes, int n_in,
                              void* d_out, int out_size) {
    const float* x  = (const float*)d_in[0];
    const float* W1 = (const float*)d_in[1];
    const float* b1 = (const float*)d_in[2];
    const float* W2 = (const float*)d_in[3];
    const float* b2 = (const float*)d_in[4];
    float* out = (float*)d_out;

    cudaFuncSetAttribute(snn_kernel,
                         cudaFuncAttributeMaxDynamicSharedMemorySize, DYN_SMEM);

    build_lut_kernel<<<(LUT_FLOATS + 255) / 256, 256>>>(W2);
    snn_kernel<<<BB / (4 * NB), 128, DYN_SMEM>>>(x, W1, b1, b2, out);
}

// round 7
// speedup vs baseline: 1.1307x; 1.1307x over previous
#include <cuda_runtime.h>

#define BB  4096
#define TT  500
#define FF  40
#define HH  128
#define OO  5
#define NB  4          // batches per warp
#define BETA 0.9f
#define THR  1.0f

#define LUT_FLOATS (OO * 16 * 256)           // 20480
#define STG_FLOATS (4 * 2 * NB * FF)         // 1280
#define DYN_SMEM   ((LUT_FLOATS + STG_FLOATS) * 4)

typedef unsigned long long u64;
typedef unsigned int u32;

__device__ float4 g_lut4[LUT_FLOATS / 4];

__device__ __forceinline__ u64 pack2(float lo, float hi) {
    u64 r; asm("mov.b64 %0, {%1, %2};" : "=l"(r) : "f"(lo), "f"(hi)); return r;
}
__device__ __forceinline__ void unpack2(u64 v, float& lo, float& hi) {
    asm("mov.b64 {%0, %1}, %2;" : "=f"(lo), "=f"(hi) : "l"(v));
}
__device__ __forceinline__ u64 fma2(u64 a, u64 b, u64 c) {
    u64 d; asm("fma.rn.f32x2 %0, %1, %2, %3;" : "=l"(d) : "l"(a), "l"(b), "l"(c)); return d;
}

// LUT[o][seg][v] = sum_{j ascending, bit j set in v} W2[o][seg*8 + j]
__global__ void build_lut_kernel(const float* __restrict__ W2) {
    const int idx = blockIdx.x * blockDim.x + threadIdx.x;
    if (idx >= LUT_FLOATS) return;
    const int v = idx & 255, seg = (idx >> 8) & 15, o = idx >> 12;
    float s = 0.f;
#pragma unroll
    for (int j = 0; j < 8; j++)
        if (v & (1 << j)) s += W2[o * HH + seg * 8 + j];
    ((float*)g_lut4)[idx] = s;
}

// Deferred layer 2 for the PREVIOUS step: byte-LUT lookups (same order as the
// rel_err=0 R5 kernel), LIF-2 update, store. Independent of the current step's
// FMA stream so ptxas can interleave them.
#define LAYER2_STORE(TPREV) do {                                               \
    float a2 = 0.f;                                                            \
    _Pragma("unroll")                                                          \
    for (int i = 0; i < 4; i++) {                                              \
        _Pragma("unroll")                                                      \
        for (int j = 0; j < 4; j++) {                                          \
            const u32 byte = (msd[i] >> (8 * j)) & 0xFFu;                      \
            const float lv = lrow[(i * 4 + j) * 256 + byte];                   \
            a2 = (i == 0 && j == 0) ? lv : (a2 + lv);                          \
        }                                                                      \
    }                                                                          \
    const float cur2 = a2 + b2l;                                               \
    const bool rst2 = m2v > THR;                                               \
    float mm = fmaf(BETA, m2v, cur2);                                          \
    if (rst2) mm -= THR;                                                       \
    m2v = mm;                                                                  \
    if (do_store)                                                              \
        __stcs(ob + (size_t)(TPREV) * BB * OO + qsel * OO + oid,               \
               (mm > THR) ? 1.0f : 0.0f);                                      \
} while (0)

// 1 warp = 4 batch elements; W1 shared in registers (8 packed-FMA chains).
// Layer-1 per-neuron accumulation order (bias first, k ascending) identical
// to the bitwise-exact R1..R5 kernels. Layer 2 via ballot + byte-LUT,
// software-pipelined one step behind layer 1.
__global__ __launch_bounds__(128, 2)
void snn_kernel(const float* __restrict__ x,  const float* __restrict__ W1,
                const float* __restrict__ b1, const float* __restrict__ b2,
                float* __restrict__ out)
{
    extern __shared__ float smem_dyn[];
    float* lut = smem_dyn;                                   // 20480 floats
    float (*sbuf)[2][NB][FF] = (float (*)[2][NB][FF])(smem_dyn + LUT_FLOATS);

    const int lane = threadIdx.x & 31;
    const int warp = threadIdx.x >> 5;
    const int b0   = (blockIdx.x * 4 + warp) * NB;

    // ---- copy LUT global -> shared (one-time) ----
    for (int i = threadIdx.x; i < LUT_FLOATS / 4; i += 128)
        ((float4*)lut)[i] = g_lut4[i];

    const int n0 = lane, n1 = lane + 32, n2 = lane + 64, n3 = lane + 96;

    // ---- W1 packed pairs in registers (shared by all 4 batches) ----
    u64 wA[FF], wB[FF];
#pragma unroll
    for (int k = 0; k < FF; k++) {
        wA[k] = pack2(W1[n0 * FF + k], W1[n1 * FF + k]);
        wB[k] = pack2(W1[n2 * FF + k], W1[n3 * FF + k]);
    }
    const u64 biasA = pack2(b1[n0], b1[n1]);
    const u64 biasB = pack2(b1[n2], b1[n3]);

    const int   oid  = lane & 7;     // output id within batch group
    const int   qsel = lane >> 3;    // which batch this lane's output belongs to
    const float b2l  = b2[oid < OO ? oid : 0];
    const bool  do_store = (oid < OO);
    const float* lrow = lut + (oid < OO ? oid : 0) * (16 * 256);

    // ---- staging map: 40 float4-chunks (4 batches x 10) over 32 lanes ----
    const int  q1i = (lane >= 30) ? 3 : (lane >= 20) ? 2 : (lane >= 10) ? 1 : 0;
    const int  r1i = lane - q1i * 10;
    const bool do2 = (lane < 8);
    const int  r2i = lane + 2;       // second chunk: batch 3, quads 2..9

    const float* xg1 = x + (size_t)(b0 + q1i) * TT * FF + r1i * 4;
    const float* xg2 = x + (size_t)(b0 + 3)   * TT * FF + r2i * 4;
    float*       ob  = out + (size_t)b0 * OO;

    float m1v[NB][4];
#pragma unroll
    for (int b = 0; b < NB; b++)
#pragma unroll
        for (int i = 0; i < 4; i++) m1v[b][i] = 0.f;
    float m2v = 0.f;
    u32 msd[4];   // deferred masks (previous step, already qsel-selected)

    // ---- de-convoy skew: ~half a step; co-resident pair (bid, bid+148)
    //      provably differs in ((bid>>2)&1) since 148>>2 = 37 is odd ----
    {
        float dummy = 1.0f;
        const int skew = ((blockIdx.x >> 2) & 1) * 288;
#pragma unroll 1
        for (int i = 0; i < skew; i++)
            asm volatile("add.f32 %0, %0, %0;" : "+f"(dummy));
        if (dummy == 1.5f) __stcs(ob, 0.0f);   // never true; keeps chain live
    }

    // ---- prologue: stage x[t=0] ----
    *((float4*)&sbuf[warp][0][q1i][r1i * 4]) = __ldcs((const float4*)xg1);
    if (do2)
        *((float4*)&sbuf[warp][0][3][r2i * 4]) = __ldcs((const float4*)xg2);
    __syncthreads();   // covers LUT copy + staging

    int stage = 0;
#pragma unroll 1
    for (int t = 0; t < TT; t++) {
        // prefetch x[t+1] (clamped)
        const int tn = (t + 1 < TT) ? t + 1 : TT - 1;
        const float4 xa = __ldcs((const float4*)(xg1 + (size_t)tn * FF));
        float4 xb;
        if (do2) xb = __ldcs((const float4*)(xg2 + (size_t)tn * FF));

        // ---- layer 1: 4 batches = 8 independent packed-FMA chains ----
        u64 acc[NB][2];
#pragma unroll
        for (int b = 0; b < NB; b++) { acc[b][0] = biasA; acc[b][1] = biasB; }
#pragma unroll
        for (int j = 0; j < FF / 4; j++) {
            float4 xq[NB];
#pragma unroll
            for (int b = 0; b < NB; b++)
                xq[b] = *((const float4*)&sbuf[warp][stage][b][j * 4]);
#pragma unroll
            for (int b = 0; b < NB; b++) {
                u64 p;
                p = pack2(xq[b].x, xq[b].x);
                acc[b][0] = fma2(p, wA[4*j+0], acc[b][0]);
                acc[b][1] = fma2(p, wB[4*j+0], acc[b][1]);
                p = pack2(xq[b].y, xq[b].y);
                acc[b][0] = fma2(p, wA[4*j+1], acc[b][0]);
                acc[b][1] = fma2(p, wB[4*j+1], acc[b][1]);
                p = pack2(xq[b].z, xq[b].z);
                acc[b][0] = fma2(p, wA[4*j+2], acc[b][0]);
                acc[b][1] = fma2(p, wB[4*j+2], acc[b][1]);
                p = pack2(xq[b].w, xq[b].w);
                acc[b][0] = fma2(p, wA[4*j+3], acc[b][0]);
                acc[b][1] = fma2(p, wB[4*j+3], acc[b][1]);
            }
        }

        // ---- deferred layer 2 for step t-1 (independent stream; ptxas can
        //      interleave its LDS/FADD/STG with the FMA block above) ----
        if (t > 0)
            LAYER2_STORE(t - 1);

        // ---- LIF layer 1 + spike masks via ballot ----
        u32 mk[NB][4];
#pragma unroll
        for (int b = 0; b < NB; b++) {
            float cur[4];
            unpack2(acc[b][0], cur[0], cur[1]);
            unpack2(acc[b][1], cur[2], cur[3]);
#pragma unroll
            for (int i = 0; i < 4; i++) {
                const bool rst = m1v[b][i] > THR;
                float m = fmaf(BETA, m1v[b][i], cur[i]);
                if (rst) m -= THR;
                m1v[b][i] = m;
                mk[b][i] = __ballot_sync(0xffffffffu, m > THR);
            }
        }
        // select this lane's batch masks; becomes next iteration's deferred state
#pragma unroll
        for (int i = 0; i < 4; i++)
            msd[i] = (qsel == 0) ? mk[0][i] : (qsel == 1) ? mk[1][i]
                   : (qsel == 2) ? mk[2][i] : mk[3][i];

        // ---- stage x[t+1] ----
        *((float4*)&sbuf[warp][stage ^ 1][q1i][r1i * 4]) = xa;
        if (do2)
            *((float4*)&sbuf[warp][stage ^ 1][3][r2i * 4]) = xb;
        __syncwarp();
        stage ^= 1;
    }

    // ---- epilogue: layer 2 for the final step ----
    LAYER2_STORE(TT - 1);
}

extern "C" void kernel_launch(void* const* d_in, const int* in_sizes, int n_in,
                              void* d_out, int out_size) {
    const float* x  = (const float*)d_in[0];
    const float* W1 = (const float*)d_in[1];
    const float* b1 = (const float*)d_in[2];
    const float* W2 = (const float*)d_in[3];
    const float* b2 = (const float*)d_in[4];
    float* out = (float*)d_out;

    cudaFuncSetAttribute(snn_kernel,
                         cudaFuncAttributeMaxDynamicSharedMemorySize, DYN_SMEM);

    build_lut_kernel<<<(LUT_FLOATS + 255) / 256, 256>>>(W2);
    snn_kernel<<<BB / (4 * NB), 128, DYN_SMEM>>>(x, W1, b1, b2, out);
}

// round 8
// speedup vs baseline: 1.1642x; 1.0296x over previous
#include <cuda_runtime.h>

#define BB  4096
#define TT  500
#define FF  40
#define HH  128
#define OO  5
#define NB  4          // max batches per warp
#define BETA 0.9f
#define THR  1.0f

#define GRID    296    // 2 CTAs on every one of 148 SMs
#define PER_CTA 14     // batches per CTA (warps: 4+3+4+3)

#define LUT_FLOATS (OO * 16 * 256)           // 20480
#define STG_FLOATS (4 * 2 * NB * FF)         // 1280
#define DYN_SMEM   ((LUT_FLOATS + STG_FLOATS) * 4)

typedef unsigned long long u64;
typedef unsigned int u32;

__device__ float4 g_lut4[LUT_FLOATS / 4];

__device__ __forceinline__ u64 pack2(float lo, float hi) {
    u64 r; asm("mov.b64 %0, {%1, %2};" : "=l"(r) : "f"(lo), "f"(hi)); return r;
}
__device__ __forceinline__ void unpack2(u64 v, float& lo, float& hi) {
    asm("mov.b64 {%0, %1}, %2;" : "=f"(lo), "=f"(hi) : "l"(v));
}
__device__ __forceinline__ u64 fma2(u64 a, u64 b, u64 c) {
    u64 d; asm("fma.rn.f32x2 %0, %1, %2, %3;" : "=l"(d) : "l"(a), "l"(b), "l"(c)); return d;
}

// LUT[o][seg][v] = sum_{j ascending, bit j set in v} W2[o][seg*8 + j]
__global__ void build_lut_kernel(const float* __restrict__ W2) {
    const int idx = blockIdx.x * blockDim.x + threadIdx.x;
    if (idx >= LUT_FLOATS) return;
    const int v = idx & 255, seg = (idx >> 8) & 15, o = idx >> 12;
    float s = 0.f;
#pragma unroll
    for (int j = 0; j < 8; j++)
        if (v & (1 << j)) s += W2[o * HH + seg * 8 + j];
    ((float*)g_lut4)[idx] = s;
}

// Whole per-timestep body for NBX batches. Byte-identical math to the
// rel_err=0 R5 kernel (layer-1 bias-first k-ascending; LUT ascending-h).
#define MAIN_LOOP(NBX)                                                         \
    _Pragma("unroll 1")                                                        \
    for (int t = 0; t < TT; t++) {                                             \
        const int tn = (t + 1 < TT) ? t + 1 : TT - 1;                          \
        const float4 xa = __ldcs((const float4*)(xg1 + (size_t)tn * FF));      \
        float4 xb;                                                             \
        if (do2) xb = __ldcs((const float4*)(xg2 + (size_t)tn * FF));          \
                                                                               \
        u64 acc[NBX][2];                                                       \
        _Pragma("unroll")                                                      \
        for (int b = 0; b < NBX; b++) { acc[b][0] = biasA; acc[b][1] = biasB; }\
        _Pragma("unroll")                                                      \
        for (int j = 0; j < FF / 4; j++) {                                     \
            float4 xq[NBX];                                                    \
            _Pragma("unroll")                                                  \
            for (int b = 0; b < NBX; b++)                                      \
                xq[b] = *((const float4*)&sbuf[warp][stage][b][j * 4]);        \
            _Pragma("unroll")                                                  \
            for (int b = 0; b < NBX; b++) {                                    \
                u64 p;                                                         \
                p = pack2(xq[b].x, xq[b].x);                                   \
                acc[b][0] = fma2(p, wA[4*j+0], acc[b][0]);                     \
                acc[b][1] = fma2(p, wB[4*j+0], acc[b][1]);                     \
                p = pack2(xq[b].y, xq[b].y);                                   \
                acc[b][0] = fma2(p, wA[4*j+1], acc[b][0]);                     \
                acc[b][1] = fma2(p, wB[4*j+1], acc[b][1]);                     \
                p = pack2(xq[b].z, xq[b].z);                                   \
                acc[b][0] = fma2(p, wA[4*j+2], acc[b][0]);                     \
                acc[b][1] = fma2(p, wB[4*j+2], acc[b][1]);                     \
                p = pack2(xq[b].w, xq[b].w);                                   \
                acc[b][0] = fma2(p, wA[4*j+3], acc[b][0]);                     \
                acc[b][1] = fma2(p, wB[4*j+3], acc[b][1]);                     \
            }                                                                  \
        }                                                                      \
                                                                               \
        u32 mk[4][4];                                                          \
        _Pragma("unroll")                                                      \
        for (int b = 0; b < NBX; b++) {                                        \
            float cur[4];                                                      \
            unpack2(acc[b][0], cur[0], cur[1]);                                \
            unpack2(acc[b][1], cur[2], cur[3]);                                \
            _Pragma("unroll")                                                  \
            for (int i = 0; i < 4; i++) {                                      \
                const bool rst = m1v[b][i] > THR;                              \
                float m = fmaf(BETA, m1v[b][i], cur[i]);                       \
                if (rst) m -= THR;                                             \
                m1v[b][i] = m;                                                 \
                mk[b][i] = __ballot_sync(0xffffffffu, m > THR);                \
            }                                                                  \
        }                                                                      \
        if (NBX < 4) {                                                         \
            _Pragma("unroll")                                                  \
            for (int i = 0; i < 4; i++) mk[3][i] = 0;                          \
        }                                                                      \
                                                                               \
        u32 ms[4];                                                             \
        _Pragma("unroll")                                                      \
        for (int i = 0; i < 4; i++)                                            \
            ms[i] = (qsel == 0) ? mk[0][i] : (qsel == 1) ? mk[1][i]            \
                  : (qsel == 2) ? mk[2][i] : mk[3][i];                         \
        float a2 = 0.f;                                                        \
        _Pragma("unroll")                                                      \
        for (int i = 0; i < 4; i++) {                                          \
            _Pragma("unroll")                                                  \
            for (int j = 0; j < 4; j++) {                                      \
                const u32 byte = (ms[i] >> (8 * j)) & 0xFFu;                   \
                const float lv = lrow[(i * 4 + j) * 256 + byte];               \
                a2 = (i == 0 && j == 0) ? lv : (a2 + lv);                      \
            }                                                                  \
        }                                                                      \
                                                                               \
        const float cur2 = a2 + b2l;                                           \
        const bool rst2 = m2v > THR;                                           \
        float mm = fmaf(BETA, m2v, cur2);                                      \
        if (rst2) mm -= THR;                                                   \
        m2v = mm;                                                              \
        if (do_store)                                                          \
            __stcs(ob + (size_t)t * BB * OO + qsel * OO + oid,                 \
                   (mm > THR) ? 1.0f : 0.0f);                                  \
                                                                               \
        *((float4*)&sbuf[warp][stage ^ 1][q1i][r1i * 4]) = xa;                 \
        if (do2)                                                               \
            *((float4*)&sbuf[warp][stage ^ 1][3][r2i * 4]) = xb;               \
        __syncwarp();                                                          \
        stage ^= 1;                                                            \
    }

// 1 warp = 4 or 3 batch elements (pattern alternates across warps AND across
// co-resident CTAs so every SMSP carries exactly 7 batches). W1 shared in
// registers (packed f32x2 pairs). Layer 2 via ballot + byte-LUT.
__global__ __launch_bounds__(128, 2)
void snn_kernel(const float* __restrict__ x,  const float* __restrict__ W1,
                const float* __restrict__ b1, const float* __restrict__ b2,
                float* __restrict__ out)
{
    extern __shared__ float smem_dyn[];
    float* lut = smem_dyn;                                   // 20480 floats
    float (*sbuf)[2][NB][FF] = (float (*)[2][NB][FF])(smem_dyn + LUT_FLOATS);

    const int lane = threadIdx.x & 31;
    const int warp = threadIdx.x >> 5;

    // ---- variable batch assignment: pattern p=(bid>>2)&1 differs between
    //      co-resident CTAs (bid, bid+148) since bit2 of 148 is set ----
    const int  p    = (blockIdx.x >> 2) & 1;
    const bool nb4  = ((warp + p) & 1) == 0;
    const int  nb   = nb4 ? 4 : 3;
    const int  b0   = blockIdx.x * PER_CTA + ((7 * warp + (p ^ 1)) >> 1);

    // ---- copy LUT global -> shared (one-time) ----
    for (int i = threadIdx.x; i < LUT_FLOATS / 4; i += 128)
        ((float4*)lut)[i] = g_lut4[i];

    const int n0 = lane, n1 = lane + 32, n2 = lane + 64, n3 = lane + 96;

    // ---- W1 packed pairs in registers ----
    u64 wA[FF], wB[FF];
#pragma unroll
    for (int k = 0; k < FF; k++) {
        wA[k] = pack2(W1[n0 * FF + k], W1[n1 * FF + k]);
        wB[k] = pack2(W1[n2 * FF + k], W1[n3 * FF + k]);
    }
    const u64 biasA = pack2(b1[n0], b1[n1]);
    const u64 biasB = pack2(b1[n2], b1[n3]);

    const int   oid  = lane & 7;     // output id within batch group
    const int   qsel = lane >> 3;    // which batch this lane's output belongs to
    const float b2l  = b2[oid < OO ? oid : 0];
    const bool  do_store = (oid < OO) && (qsel < nb) && (b0 + qsel < BB);
    const float* lrow = lut + (oid < OO ? oid : 0) * (16 * 256);

    // ---- staging map: 40 float4-chunks (4 batches x 10) over 32 lanes ----
    const int  q1i = (lane >= 30) ? 3 : (lane >= 20) ? 2 : (lane >= 10) ? 1 : 0;
    const int  r1i = lane - q1i * 10;
    const bool do2 = (lane < 8);
    const int  r2i = lane + 2;       // second chunk: batch 3, quads 2..9

    const int bq1 = (b0 + q1i < BB) ? (b0 + q1i) : (BB - 1);
    const int bq2 = (b0 + 3   < BB) ? (b0 + 3)   : (BB - 1);
    const float* xg1 = x + (size_t)bq1 * TT * FF + r1i * 4;
    const float* xg2 = x + (size_t)bq2 * TT * FF + r2i * 4;
    float*       ob  = out + (size_t)b0 * OO;

    float m1v[NB][4];
#pragma unroll
    for (int b = 0; b < NB; b++)
#pragma unroll
        for (int i = 0; i < 4; i++) m1v[b][i] = 0.f;
    float m2v = 0.f;

    // ---- de-convoy skew (same bit as pattern p) ----
    {
        float dummy = 1.0f;
        const int skew = p * 96;
#pragma unroll 1
        for (int i = 0; i < skew; i++)
            asm volatile("add.f32 %0, %0, %0;" : "+f"(dummy));
        if (dummy == 1.5f) __stcs(ob, 0.0f);   // never true; keeps chain live
    }

    // ---- prologue: stage x[t=0] ----
    *((float4*)&sbuf[warp][0][q1i][r1i * 4]) = __ldcs((const float4*)xg1);
    if (do2)
        *((float4*)&sbuf[warp][0][3][r2i * 4]) = __ldcs((const float4*)xg2);
    __syncthreads();   // covers LUT copy + staging

    int stage = 0;
    if (nb4) {
        MAIN_LOOP(4)
    } else {
        MAIN_LOOP(3)
    }
}

extern "C" void kernel_launch(void* const* d_in, const int* in_sizes, int n_in,
                              void* d_out, int out_size) {
    const float* x  = (const float*)d_in[0];
    const float* W1 = (const float*)d_in[1];
    const float* b1 = (const float*)d_in[2];
    const float* W2 = (const float*)d_in[3];
    const float* b2 = (const float*)d_in[4];
    float* out = (float*)d_out;

    cudaFuncSetAttribute(snn_kernel,
                         cudaFuncAttributeMaxDynamicSharedMemorySize, DYN_SMEM);

    build_lut_kernel<<<(LUT_FLOATS + 255) / 256, 256>>>(W2);
    snn_kernel<<<GRID, 128, DYN_SMEM>>>(x, W1, b1, b2, out);
}

// round 9
// speedup vs baseline: 1.4051x; 1.2069x over previous
#include <cuda_runtime.h>

#define BB  4096
#define TT  500
#define FF  40
#define HH  128
#define OO  5
#define NB  4          // batches per warp
#define BETA 0.9f
#define THR  1.0f

// Per-output LUT stride padded 4096 -> 4100 words (4100 % 32 = 4) so the five
// o-rows land on different banks: bank = (4*o + byte) % 32 instead of byte % 32.
#define O_STRIDE   (16 * 256 + 4)               // 4100
#define LUT_FLOATS (OO * O_STRIDE)              // 20500 (divisible by 4)
#define STG_FLOATS (4 * 2 * NB * FF)            // 1280
#define DYN_SMEM   ((LUT_FLOATS + STG_FLOATS) * 4)

typedef unsigned long long u64;
typedef unsigned int u32;

__device__ float4 g_lut4[LUT_FLOATS / 4];

__device__ __forceinline__ u64 pack2(float lo, float hi) {
    u64 r; asm("mov.b64 %0, {%1, %2};" : "=l"(r) : "f"(lo), "f"(hi)); return r;
}
__device__ __forceinline__ void unpack2(u64 v, float& lo, float& hi) {
    asm("mov.b64 {%0, %1}, %2;" : "=f"(lo), "=f"(hi) : "l"(v));
}
__device__ __forceinline__ u64 fma2(u64 a, u64 b, u64 c) {
    u64 d; asm("fma.rn.f32x2 %0, %1, %2, %3;" : "=l"(d) : "l"(a), "l"(b), "l"(c)); return d;
}

// LUT[o][seg][v] = sum_{j ascending, bit j set in v} W2[o][seg*8 + j]
// stored with padded per-o stride O_STRIDE.
__global__ void build_lut_kernel(const float* __restrict__ W2) {
    const int idx = blockIdx.x * blockDim.x + threadIdx.x;
    if (idx >= OO * 16 * 256) return;
    const int v = idx & 255, seg = (idx >> 8) & 15, o = idx >> 12;
    float s = 0.f;
#pragma unroll
    for (int j = 0; j < 8; j++)
        if (v & (1 << j)) s += W2[o * HH + seg * 8 + j];
    ((float*)g_lut4)[o * O_STRIDE + seg * 256 + v] = s;
}

// 1 warp = 4 batch elements; W1 shared in registers (8 packed-FMA chains).
// Layer-1 per-neuron accumulation order (bias first, k ascending) identical
// to the bitwise-exact R1..R5 kernels. Layer 2 via ballot + byte-LUT
// (identical arithmetic to rel_err=0 R5; only LUT addressing is padded).
__global__ __launch_bounds__(128, 2)
void snn_kernel(const float* __restrict__ x,  const float* __restrict__ W1,
                const float* __restrict__ b1, const float* __restrict__ b2,
                float* __restrict__ out)
{
    extern __shared__ float smem_dyn[];
    float* lut = smem_dyn;                                   // 20500 floats
    float (*sbuf)[2][NB][FF] = (float (*)[2][NB][FF])(smem_dyn + LUT_FLOATS);

    const int lane = threadIdx.x & 31;
    const int warp = threadIdx.x >> 5;
    const int b0   = (blockIdx.x * 4 + warp) * NB;

    // ---- copy LUT global -> shared (one-time) ----
    for (int i = threadIdx.x; i < LUT_FLOATS / 4; i += 128)
        ((float4*)lut)[i] = g_lut4[i];

    const int n0 = lane, n1 = lane + 32, n2 = lane + 64, n3 = lane + 96;

    // ---- W1 packed pairs in registers (shared by all 4 batches) ----
    u64 wA[FF], wB[FF];
#pragma unroll
    for (int k = 0; k < FF; k++) {
        wA[k] = pack2(W1[n0 * FF + k], W1[n1 * FF + k]);
        wB[k] = pack2(W1[n2 * FF + k], W1[n3 * FF + k]);
    }
    const u64 biasA = pack2(b1[n0], b1[n1]);
    const u64 biasB = pack2(b1[n2], b1[n3]);

    const int   oid  = lane & 7;     // output id within batch group
    const int   qsel = lane >> 3;    // which batch this lane's output belongs to
    const float b2l  = b2[oid < OO ? oid : 0];
    const bool  do_store = (oid < OO);
    const float* lrow = lut + (oid < OO ? oid : 0) * O_STRIDE;

    // ---- staging map: 40 float4-chunks (4 batches x 10) over 32 lanes ----
    const int  q1i = (lane >= 30) ? 3 : (lane >= 20) ? 2 : (lane >= 10) ? 1 : 0;
    const int  r1i = lane - q1i * 10;
    const bool do2 = (lane < 8);
    const int  r2i = lane + 2;       // second chunk: batch 3, quads 2..9

    const float* xg1 = x + (size_t)(b0 + q1i) * TT * FF + r1i * 4;
    const float* xg2 = x + (size_t)(b0 + 3)   * TT * FF + r2i * 4;
    float*       ob  = out + (size_t)b0 * OO;

    float m1v[NB][4];
#pragma unroll
    for (int b = 0; b < NB; b++)
#pragma unroll
        for (int i = 0; i < 4; i++) m1v[b][i] = 0.f;
    float m2v = 0.f;

    // ---- de-convoy skew: co-resident CTA pair likely differs in bit 2 ----
    {
        float dummy = 1.0f;
        const int skew = ((blockIdx.x >> 2) & 1) * 96;
#pragma unroll 1
        for (int i = 0; i < skew; i++)
            asm volatile("add.f32 %0, %0, %0;" : "+f"(dummy));
        if (dummy == 1.5f) __stcs(ob, 0.0f);   // never true; keeps chain live
    }

    // ---- prologue: stage x[t=0] ----
    *((float4*)&sbuf[warp][0][q1i][r1i * 4]) = __ldcs((const float4*)xg1);
    if (do2)
        *((float4*)&sbuf[warp][0][3][r2i * 4]) = __ldcs((const float4*)xg2);
    __syncthreads();   // covers LUT copy + staging

    int stage = 0;
#pragma unroll 1
    for (int t = 0; t < TT; t++) {
        // prefetch x[t+1] (clamped)
        const int tn = (t + 1 < TT) ? t + 1 : TT - 1;
        const float4 xa = __ldcs((const float4*)(xg1 + (size_t)tn * FF));
        float4 xb;
        if (do2) xb = __ldcs((const float4*)(xg2 + (size_t)tn * FF));

        // ---- layer 1: 4 batches = 8 independent packed-FMA chains ----
        u64 acc[NB][2];
#pragma unroll
        for (int b = 0; b < NB; b++) { acc[b][0] = biasA; acc[b][1] = biasB; }
#pragma unroll
        for (int j = 0; j < FF / 4; j++) {
            float4 xq[NB];
#pragma unroll
            for (int b = 0; b < NB; b++)
                xq[b] = *((const float4*)&sbuf[warp][stage][b][j * 4]);
#pragma unroll
            for (int b = 0; b < NB; b++) {
                u64 p;
                p = pack2(xq[b].x, xq[b].x);
                acc[b][0] = fma2(p, wA[4*j+0], acc[b][0]);
                acc[b][1] = fma2(p, wB[4*j+0], acc[b][1]);
                p = pack2(xq[b].y, xq[b].y);
                acc[b][0] = fma2(p, wA[4*j+1], acc[b][0]);
                acc[b][1] = fma2(p, wB[4*j+1], acc[b][1]);
                p = pack2(xq[b].z, xq[b].z);
                acc[b][0] = fma2(p, wA[4*j+2], acc[b][0]);
                acc[b][1] = fma2(p, wB[4*j+2], acc[b][1]);
                p = pack2(xq[b].w, xq[b].w);
                acc[b][0] = fma2(p, wA[4*j+3], acc[b][0]);
                acc[b][1] = fma2(p, wB[4*j+3], acc[b][1]);
            }
        }

        // ---- LIF layer 1 + spike masks via ballot ----
        u32 mk[NB][4];
#pragma unroll
        for (int b = 0; b < NB; b++) {
            float cur[4];
            unpack2(acc[b][0], cur[0], cur[1]);
            unpack2(acc[b][1], cur[2], cur[3]);
#pragma unroll
            for (int i = 0; i < 4; i++) {
                const bool rst = m1v[b][i] > THR;
                float m = fmaf(BETA, m1v[b][i], cur[i]);
                if (rst) m -= THR;
                m1v[b][i] = m;
                mk[b][i] = __ballot_sync(0xffffffffu, m > THR);
            }
        }

        // ---- layer 2: byte-LUT lookups (ascending-h order) ----
        u32 ms[4];
#pragma unroll
        for (int i = 0; i < 4; i++)
            ms[i] = (qsel == 0) ? mk[0][i] : (qsel == 1) ? mk[1][i]
                  : (qsel == 2) ? mk[2][i] : mk[3][i];
        float a2 = 0.f;
#pragma unroll
        for (int i = 0; i < 4; i++) {
#pragma unroll
            for (int j = 0; j < 4; j++) {
                const u32 byte = (ms[i] >> (8 * j)) & 0xFFu;
                const float lv = lrow[(i * 4 + j) * 256 + byte];
                a2 = (i == 0 && j == 0) ? lv : (a2 + lv);
            }
        }

        // ---- LIF layer 2 + store (20 lanes active) ----
        const float cur2 = a2 + b2l;
        const bool rst2 = m2v > THR;
        float mm = fmaf(BETA, m2v, cur2);
        if (rst2) mm -= THR;
        m2v = mm;
        if (do_store)
            __stcs(ob + (size_t)t * BB * OO + qsel * OO + oid,
                   (mm > THR) ? 1.0f : 0.0f);

        // ---- stage x[t+1] ----
        *((float4*)&sbuf[warp][stage ^ 1][q1i][r1i * 4]) = xa;
        if (do2)
            *((float4*)&sbuf[warp][stage ^ 1][3][r2i * 4]) = xb;
        __syncwarp();
        stage ^= 1;
    }
}

extern "C" void kernel_launch(void* const* d_in, const int* in_sizes, int n_in,
                              void* d_out, int out_size) {
    const float* x  = (const float*)d_in[0];
    const float* W1 = (const float*)d_in[1];
    const float* b1 = (const float*)d_in[2];
    const float* W2 = (const float*)d_in[3];
    const float* b2 = (const float*)d_in[4];
    float* out = (float*)d_out;

    cudaFuncSetAttribute(snn_kernel,
                         cudaFuncAttributeMaxDynamicSharedMemorySize, DYN_SMEM);

    build_lut_kernel<<<(OO * 16 * 256 + 255) / 256, 256>>>(W2);
    snn_kernel<<<BB / (4 * NB), 128, DYN_SMEM>>>(x, W1, b1, b2, out);
}

// round 10
// speedup vs baseline: 1.4057x; 1.0004x over previous
#include <cuda_runtime.h>

#define BB  4096
#define TT  500
#define FF  40
#define HH  128
#define OO  5
#define NB  4          // batches per warp
#define BETA 0.9f
#define THR  1.0f

// Per-output LUT stride padded 4096 -> 4100 words (4100 % 32 = 4) so the five
// o-rows land on different banks: bank = (4*o + byte) % 32 instead of byte % 32.
#define O_STRIDE   (16 * 256 + 4)               // 4100
#define LUT_FLOATS (OO * O_STRIDE)              // 20500 (divisible by 4)
#define STG_FLOATS (4 * 2 * NB * FF)            // 1280
#define DYN_SMEM   ((LUT_FLOATS + STG_FLOATS) * 4)

typedef unsigned long long u64;
typedef unsigned int u32;

__device__ float4 g_lut4[LUT_FLOATS / 4];
__device__ u32    g_tick[256];   // per-SM arrival tickets (parity used; accumulates harmlessly)

__device__ __forceinline__ u64 pack2(float lo, float hi) {
    u64 r; asm("mov.b64 %0, {%1, %2};" : "=l"(r) : "f"(lo), "f"(hi)); return r;
}
__device__ __forceinline__ void unpack2(u64 v, float& lo, float& hi) {
    asm("mov.b64 {%0, %1}, %2;" : "=f"(lo), "=f"(hi) : "l"(v));
}
__device__ __forceinline__ u64 fma2(u64 a, u64 b, u64 c) {
    u64 d; asm("fma.rn.f32x2 %0, %1, %2, %3;" : "=l"(d) : "l"(a), "l"(b), "l"(c)); return d;
}

// LUT[o][seg][v] = sum_{j ascending, bit j set in v} W2[o][seg*8 + j]
// stored with padded per-o stride O_STRIDE.
__global__ void build_lut_kernel(const float* __restrict__ W2) {
    const int idx = blockIdx.x * blockDim.x + threadIdx.x;
    if (idx >= OO * 16 * 256) return;
    const int v = idx & 255, seg = (idx >> 8) & 15, o = idx >> 12;
    float s = 0.f;
#pragma unroll
    for (int j = 0; j < 8; j++)
        if (v & (1 << j)) s += W2[o * HH + seg * 8 + j];
    ((float*)g_lut4)[o * O_STRIDE + seg * 256 + v] = s;
}

// 1 warp = 4 batch elements; W1 shared in registers (8 packed-FMA chains).
// Layer-1 per-neuron accumulation order (bias first, k ascending) identical
// to the bitwise-exact R1..R9 kernels. Layer 2 via ballot + byte-LUT with
// bank-conflict-free padded stride (identical arithmetic to rel_err=0 R9).
// Co-resident CTA pairs are anti-phased via a per-SM ticket so each SMSP's
// two warps overlap FMA blocks with serial tails instead of convoying.
__global__ __launch_bounds__(128, 2)
void snn_kernel(const float* __restrict__ x,  const float* __restrict__ W1,
                const float* __restrict__ b1, const float* __restrict__ b2,
                float* __restrict__ out)
{
    extern __shared__ float smem_dyn[];
    float* lut = smem_dyn;                                   // 20500 floats
    float (*sbuf)[2][NB][FF] = (float (*)[2][NB][FF])(smem_dyn + LUT_FLOATS);
    __shared__ u32 rank_sh;

    const int lane = threadIdx.x & 31;
    const int warp = threadIdx.x >> 5;
    const int b0   = (blockIdx.x * 4 + warp) * NB;

    // ---- per-SM arrival ticket: co-resident CTAs get opposite parity ----
    if (threadIdx.x == 0) {
        u32 smid; asm volatile("mov.u32 %0, %%smid;" : "=r"(smid));
        rank_sh = atomicAdd(&g_tick[smid & 255], 1u) & 1u;
    }

    // ---- copy LUT global -> shared (one-time) ----
    for (int i = threadIdx.x; i < LUT_FLOATS / 4; i += 128)
        ((float4*)lut)[i] = g_lut4[i];

    const int n0 = lane, n1 = lane + 32, n2 = lane + 64, n3 = lane + 96;

    // ---- W1 packed pairs in registers (shared by all 4 batches) ----
    u64 wA[FF], wB[FF];
#pragma unroll
    for (int k = 0; k < FF; k++) {
        wA[k] = pack2(W1[n0 * FF + k], W1[n1 * FF + k]);
        wB[k] = pack2(W1[n2 * FF + k], W1[n3 * FF + k]);
    }
    const u64 biasA = pack2(b1[n0], b1[n1]);
    const u64 biasB = pack2(b1[n2], b1[n3]);

    const int   oid  = lane & 7;     // output id within batch group
    const int   qsel = lane >> 3;    // which batch this lane's output belongs to
    const float b2l  = b2[oid < OO ? oid : 0];
    const bool  do_store = (oid < OO);
    const float* lrow = lut + (oid < OO ? oid : 0) * O_STRIDE;

    // ---- staging map: 40 float4-chunks (4 batches x 10) over 32 lanes ----
    const int  q1i = (lane >= 30) ? 3 : (lane >= 20) ? 2 : (lane >= 10) ? 1 : 0;
    const int  r1i = lane - q1i * 10;
    const bool do2 = (lane < 8);
    const int  r2i = lane + 2;       // second chunk: batch 3, quads 2..9

    const float* xg1 = x + (size_t)(b0 + q1i) * TT * FF + r1i * 4;
    const float* xg2 = x + (size_t)(b0 + 3)   * TT * FF + r2i * 4;

    float m1v[NB][4];
#pragma unroll
    for (int b = 0; b < NB; b++)
#pragma unroll
        for (int i = 0; i < 4; i++) m1v[b][i] = 0.f;
    float m2v = 0.f;

    // ---- prologue: stage x[t=0] ----
    *((float4*)&sbuf[warp][0][q1i][r1i * 4]) = __ldcs((const float4*)xg1);
    if (do2)
        *((float4*)&sbuf[warp][0][3][r2i * 4]) = __ldcs((const float4*)xg2);
    __syncthreads();   // covers LUT copy + staging + rank_sh

    // ---- anti-phase skew: rank-1 CTA delays ~half a step (dependent FADDs).
    //      No loop syncs follow, so the SMSP warp pair stays anti-phased. ----
    {
        float dummy = 1.0f;
        const int skew = (int)rank_sh * 256;
#pragma unroll 1
        for (int i = 0; i < skew; i++)
            asm volatile("add.f32 %0, %0, %0;" : "+f"(dummy));
        if (dummy == 1.5f)   // never true; keeps the chain live
            out[(size_t)BB * OO * TT - 1] = 0.0f;
    }

    // output pointer, strength-reduced (advances by BB*OO per step)
    float* op = out + (size_t)b0 * OO + qsel * OO + oid;

    int stage = 0;
#pragma unroll 1
    for (int t = 0; t < TT; t++) {
        // prefetch x[t+1] (clamped)
        const int tn = (t + 1 < TT) ? t + 1 : TT - 1;
        const float4 xa = __ldcs((const float4*)(xg1 + (size_t)tn * FF));
        float4 xb;
        if (do2) xb = __ldcs((const float4*)(xg2 + (size_t)tn * FF));

        // ---- layer 1: 4 batches = 8 independent packed-FMA chains ----
        u64 acc[NB][2];
#pragma unroll
        for (int b = 0; b < NB; b++) { acc[b][0] = biasA; acc[b][1] = biasB; }
#pragma unroll
        for (int j = 0; j < FF / 4; j++) {
            float4 xq[NB];
#pragma unroll
            for (int b = 0; b < NB; b++)
                xq[b] = *((const float4*)&sbuf[warp][stage][b][j * 4]);
#pragma unroll
            for (int b = 0; b < NB; b++) {
                u64 p;
                p = pack2(xq[b].x, xq[b].x);
                acc[b][0] = fma2(p, wA[4*j+0], acc[b][0]);
                acc[b][1] = fma2(p, wB[4*j+0], acc[b][1]);
                p = pack2(xq[b].y, xq[b].y);
                acc[b][0] = fma2(p, wA[4*j+1], acc[b][0]);
                acc[b][1] = fma2(p, wB[4*j+1], acc[b][1]);
                p = pack2(xq[b].z, xq[b].z);
                acc[b][0] = fma2(p, wA[4*j+2], acc[b][0]);
                acc[b][1] = fma2(p, wB[4*j+2], acc[b][1]);
                p = pack2(xq[b].w, xq[b].w);
                acc[b][0] = fma2(p, wA[4*j+3], acc[b][0]);
                acc[b][1] = fma2(p, wB[4*j+3], acc[b][1]);
            }
        }

        // ---- LIF layer 1 + spike masks via ballot ----
        u32 mk[NB][4];
#pragma unroll
        for (int b = 0; b < NB; b++) {
            float cur[4];
            unpack2(acc[b][0], cur[0], cur[1]);
            unpack2(acc[b][1], cur[2], cur[3]);
#pragma unroll
            for (int i = 0; i < 4; i++) {
                const bool rst = m1v[b][i] > THR;
                float m = fmaf(BETA, m1v[b][i], cur[i]);
                if (rst) m -= THR;
                m1v[b][i] = m;
                mk[b][i] = __ballot_sync(0xffffffffu, m > THR);
            }
        }

        // ---- layer 2: byte-LUT lookups (ascending-h order) ----
        u32 ms[4];
#pragma unroll
        for (int i = 0; i < 4; i++)
            ms[i] = (qsel == 0) ? mk[0][i] : (qsel == 1) ? mk[1][i]
                  : (qsel == 2) ? mk[2][i] : mk[3][i];
        float a2 = 0.f;
#pragma unroll
        for (int i = 0; i < 4; i++) {
#pragma unroll
            for (int j = 0; j < 4; j++) {
                const u32 byte = (ms[i] >> (8 * j)) & 0xFFu;
                const float lv = lrow[(i * 4 + j) * 256 + byte];
                a2 = (i == 0 && j == 0) ? lv : (a2 + lv);
            }
        }

        // ---- LIF layer 2 + store (20 lanes active) ----
        const float cur2 = a2 + b2l;
        const bool rst2 = m2v > THR;
        float mm = fmaf(BETA, m2v, cur2);
        if (rst2) mm -= THR;
        m2v = mm;
        if (do_store)
            __stcs(op, (mm > THR) ? 1.0f : 0.0f);
        op += BB * OO;

        // ---- stage x[t+1] ----
        *((float4*)&sbuf[warp][stage ^ 1][q1i][r1i * 4]) = xa;
        if (do2)
            *((float4*)&sbuf[warp][stage ^ 1][3][r2i * 4]) = xb;
        __syncwarp();
        stage ^= 1;
    }
}

extern "C" void kernel_launch(void* const* d_in, const int* in_sizes, int n_in,
                              void* d_out, int out_size) {
    const float* x  = (const float*)d_in[0];
    const float* W1 = (const float*)d_in[1];
    const float* b1 = (const float*)d_in[2];
    const float* W2 = (const float*)d_in[3];
    const float* b2 = (const float*)d_in[4];
    float* out = (float*)d_out;

    cudaFuncSetAttribute(snn_kernel,
                         cudaFuncAttributeMaxDynamicSharedMemorySize, DYN_SMEM);

    build_lut_kernel<<<(OO * 16 * 256 + 255) / 256, 256>>>(W2);
    snn_kernel<<<BB / (4 * NB), 128, DYN_SMEM>>>(x, W1, b1, b2, out);
}